// round 15
// baseline (speedup 1.0000x reference)
#include <cuda_runtime.h>

#define NUM_MODELS 64
#define IN_F 6
#define HID 64
#define OUT_F 3
#define B_MAX 131072
#define K_CHUNKS 4
#define TPB_MLP 256
#define RT 64      // rows per tile
#define WP 68      // padded weight row stride (transposed layout, conflict-free)

typedef unsigned long long u64;

// -------- scratch (no allocations allowed; __device__ globals) --------
__device__ int g_counts[NUM_MODELS];
__device__ int g_offsets[NUM_MODELS];
__device__ int g_reserve[NUM_MODELS];
__device__ int g_rowids[B_MAX];
__device__ unsigned char g_idx[B_MAX];

// -------- smem float offsets for k_mlp --------
#define OF_W0 0                       // 6*68 = 408 -> pad 416
#define OF_W1 416                     // 64*68 = 4352
#define OF_W2 4768
#define OF_W3 9120
#define OF_W4 13472                   // 3*68 = 204 -> pad to 13680
#define OF_B  13680                   // b0..b3 (64 each) + b4 (3) -> pad 13952
#define OF_RID 13952                  // 64 ints (row ids of current tile)
#define OF_A0 14016                   // 64*64 act ping
#define OF_A1 18112                   // 64*64 act pong
#define SMEM_FLOATS 22208
#define SMEM_BYTES (SMEM_FLOATS * 4)  // 88832 B -> 2 CTAs/SM (x256 thr)

// ---- packed f32x2 kept in 64-bit registers end-to-end ----
__device__ __forceinline__ u64 ffma2u(u64 a, u64 b, u64 c) {
    u64 d;
    asm("fma.rn.f32x2 %0, %1, %2, %3;" : "=l"(d) : "l"(a), "l"(b), "l"(c));
    return d;
}
__device__ __forceinline__ void unpack2(u64 v, float& lo, float& hi) {
    asm("mov.b64 {%0, %1}, %2;" : "=f"(lo), "=f"(hi) : "l"(v));
}
__device__ __forceinline__ u64 pack2(float lo, float hi) {
    u64 d;
    asm("mov.b64 %0, {%1, %2};" : "=l"(d) : "f"(lo), "f"(hi));
    return d;
}

// ---------------------------------------------------------------------
// Kernel 1: zero histogram/reservations + fill constant outputs
// ---------------------------------------------------------------------
__global__ void k_fill(float* __restrict__ out_logits,
                       float* __restrict__ out_probs, int n4) {
    if (blockIdx.x == 0 && threadIdx.x < NUM_MODELS) {
        g_counts[threadIdx.x] = 0;
        g_reserve[threadIdx.x] = 0;
    }
    int gid = blockIdx.x * blockDim.x + threadIdx.x;
    int stride = gridDim.x * blockDim.x;
    float4 ones = make_float4(1.f, 1.f, 1.f, 1.f);
    float4 prob = make_float4(0.015625f, 0.015625f, 0.015625f, 0.015625f);
    float4* L = (float4*)out_logits;
    float4* P = (float4*)out_probs;
    for (int i = gid; i < n4; i += stride) {
        L[i] = ones;
        P[i] = prob;
    }
}

// ---------------------------------------------------------------------
// Kernel 2: selection index per row; SMEM histogram -> 1 global atomic
// per (CTA, model). Correctly-rounded intrinsics (fast-math immune).
// ---------------------------------------------------------------------
__global__ void k_index(const float* __restrict__ in,
                        float* __restrict__ out_idx, int B) {
    __shared__ int hist[NUM_MODELS];
    if (threadIdx.x < NUM_MODELS) hist[threadIdx.x] = 0;
    __syncthreads();

    const float TWO_PI = 6.28318530717958647692f;
    int gid = blockIdx.x * blockDim.x + threadIdx.x;
    int stride = gridDim.x * blockDim.x;
    for (int r = gid; r < B; r += stride) {
        float x0 = in[6 * r + 0];
        float x2 = in[6 * r + 2];
        float ang = atan2f(x2, x0);
        float a = fmodf(__fadd_rn(ang, TWO_PI), TWO_PI);  // positive args: mod==fmod
        a = __fmul_rn(__fdiv_rn(a, TWO_PI), 64.0f);
        float f = floorf(a);
        int idx = (int)f;
        int idxw = idx > 63 ? 63 : (idx < 0 ? 0 : idx);   // XLA gather clamps OOB
        g_idx[r] = (unsigned char)idxw;
        out_idx[r] = f;                                   // selection_indices (as f32)
        atomicAdd(&hist[idxw], 1);
    }
    __syncthreads();
    if (threadIdx.x < NUM_MODELS) {
        int c = hist[threadIdx.x];
        if (c) atomicAdd(&g_counts[threadIdx.x], c);
    }
}

// ---------------------------------------------------------------------
// Kernel 3: scatter rows into buckets (scan folded in; block 0 publishes
// g_offsets). Two-pass per CTA: count -> reserve range -> write.
// ---------------------------------------------------------------------
__global__ void k_scatter(int B) {
    __shared__ int hist[NUM_MODELS];
    __shared__ int sbase[NUM_MODELS];
    __shared__ int soff[NUM_MODELS];
    int per = (B + gridDim.x - 1) / gridDim.x;
    int r0 = blockIdx.x * per;
    int r1 = r0 + per;
    if (r1 > B) r1 = B;

    if (threadIdx.x < NUM_MODELS) {
        hist[threadIdx.x] = 0;
        soff[threadIdx.x] = g_counts[threadIdx.x];
    }
    __syncthreads();
    if (threadIdx.x == 0) {
        int run = 0;
        for (int m = 0; m < NUM_MODELS; m++) {
            int c = soff[m];
            soff[m] = run;
            run += c;
        }
    }
    __syncthreads();
    if (blockIdx.x == 0 && threadIdx.x < NUM_MODELS)
        g_offsets[threadIdx.x] = soff[threadIdx.x];

    for (int r = r0 + threadIdx.x; r < r1; r += blockDim.x)
        atomicAdd(&hist[g_idx[r]], 1);
    __syncthreads();
    if (threadIdx.x < NUM_MODELS) {
        int c = hist[threadIdx.x];
        sbase[threadIdx.x] =
            soff[threadIdx.x] + (c ? atomicAdd(&g_reserve[threadIdx.x], c) : 0);
        hist[threadIdx.x] = 0;
    }
    __syncthreads();
    for (int r = r0 + threadIdx.x; r < r1; r += blockDim.x) {
        int m = g_idx[r];
        g_rowids[sbase[m] + atomicAdd(&hist[m], 1)] = r;
    }
}

// ---------------------------------------------------------------------
// GEMM tile (256 threads): 64 rows x 64 outs x K. Thread = 2 rows x
// 8 outs; accs pair over outs so weight LDS.128 yields FFMA2 operands
// directly; activations load as float2 (no unpack). Per k-step:
// 3 LDS + 4 MOV + 8 FFMA2 -> fma-issue fraction ~0.44 (89% of pipe cap).
// tx = tid&31 -> rows 2tx,2tx+1; wid = tid>>5 -> outs wid*8.. (w loads
// warp-broadcast). Same k-order/out-pairing as before -> identical FP.
// ---------------------------------------------------------------------
template <int K>
__device__ __forceinline__ void gemm_tile(const float* __restrict__ wT,
                                          const float* __restrict__ aIn,
                                          float* __restrict__ aOut,
                                          const float* __restrict__ bias,
                                          int tx, int wid) {
    u64 acc[2][4];
#pragma unroll
    for (int p = 0; p < 4; p++) {
        u64 bp = *(const u64*)(bias + wid * 8 + 2 * p);
        acc[0][p] = bp;
        acc[1][p] = bp;
    }
    const float* ap = aIn + tx * 2;
    const float* wp = wT + wid * 8;
#pragma unroll 4
    for (int k = 0; k < K; k++) {
        float2 f = *(const float2*)(ap + k * RT);
        ulonglong2 wq0 = *(const ulonglong2*)(wp + k * WP);
        ulonglong2 wq1 = *(const ulonglong2*)(wp + k * WP + 4);
        u64 d0 = pack2(f.x, f.x);
        u64 d1 = pack2(f.y, f.y);
        u64 wv[4] = {wq0.x, wq0.y, wq1.x, wq1.y};
#pragma unroll
        for (int p = 0; p < 4; p++) {
            acc[0][p] = ffma2u(wv[p], d0, acc[0][p]);
            acc[1][p] = ffma2u(wv[p], d1, acc[1][p]);
        }
    }
#pragma unroll
    for (int r = 0; r < 2; r++) {
        int row = tx * 2 + r;
#pragma unroll
        for (int p = 0; p < 4; p++) {
            float v0, v1;
            unpack2(acc[r][p], v0, v1);
            int o = wid * 8 + 2 * p;
            aOut[o * RT + row] = fmaxf(v0, 0.f);
            aOut[(o + 1) * RT + row] = fmaxf(v1, 0.f);
        }
    }
}

// ---------------------------------------------------------------------
// Kernel 4: bucketed MLP as tiled GEMMs. One model per CTA (256 thr);
// 2 CTAs/SM -> 4 warps/SMSP (was 2: both-stalled bubbles dominated,
// fma=37% issue=36% in R13). Next tile's gather LDGs prefetched into
// registers before the GEMM chain; final layer parallel (2 thr/row).
// ---------------------------------------------------------------------
__global__ void __launch_bounds__(TPB_MLP)
k_mlp(const float* __restrict__ inputs,
      const float* __restrict__ w0, const float* __restrict__ b0,
      const float* __restrict__ w1, const float* __restrict__ b1,
      const float* __restrict__ w2, const float* __restrict__ b2,
      const float* __restrict__ w3, const float* __restrict__ b3,
      const float* __restrict__ w4, const float* __restrict__ b4,
      float* __restrict__ out_model, float* __restrict__ out_top) {
    extern __shared__ float s[];
    int tid = threadIdx.x;
    int m = blockIdx.x / K_CHUNKS;
    int chunk = blockIdx.x % K_CHUNKS;
    int tx = tid & 31, wid = tid >> 5;
    int* srid = (int*)(s + OF_RID);

    // ---- stage weights (transposed) + biases ----
    {
        const float* srcs[3] = {w1 + m * 4096, w2 + m * 4096, w3 + m * 4096};
        float* dsts[3] = {s + OF_W1, s + OF_W2, s + OF_W3};
#pragma unroll
        for (int l = 0; l < 3; l++) {
            const float* src = srcs[l];
            float* dst = dsts[l];
            for (int idx = tid; idx < 4096; idx += TPB_MLP) {
                int o = idx >> 6, k = idx & 63;
                dst[k * WP + o] = src[idx];
            }
        }
        for (int idx = tid; idx < 384; idx += TPB_MLP) {
            int o = idx / 6, i = idx % 6;
            s[OF_W0 + i * WP + o] = w0[m * 384 + idx];
        }
        for (int idx = tid; idx < 192; idx += TPB_MLP) {
            int o = idx >> 6, k = idx & 63;
            s[OF_W4 + o * WP + k] = w4[m * 192 + idx];  // row-major, broadcast reads
        }
        if (tid < 64) {
            s[OF_B + tid] = b0[m * 64 + tid];
            s[OF_B + 64 + tid] = b1[m * 64 + tid];
            s[OF_B + 128 + tid] = b2[m * 64 + tid];
            s[OF_B + 192 + tid] = b3[m * 64 + tid];
        }
        if (tid < OUT_F) s[OF_B + 256 + tid] = b4[m * 3 + tid];
    }

    int count = g_counts[m];
    int off = g_offsets[m];

    // ---- prefetch tile 0's gather into registers ----
    int prid = 0;
    float2 pa = {0.f, 0.f}, pb = {0.f, 0.f}, pc = {0.f, 0.f};
    if (tid < RT) {
        int j = chunk * RT + tid;
        if (j < count) {
            prid = g_rowids[off + j];
            const float2* ip = (const float2*)(inputs + 6 * prid);
            pa = ip[0]; pb = ip[1]; pc = ip[2];
        }
    }

    for (int tb = chunk * RT; tb < count; tb += K_CHUNKS * RT) {
        int nrows = count - tb;
        if (nrows > RT) nrows = RT;
        __syncthreads();  // staging / prev tile's final-layer A0 reads done

        // commit prefetched gather -> A0[k][row], then kick next prefetch
        if (tid < RT) {
            s[OF_A0 + 0 * RT + tid] = pa.x;
            s[OF_A0 + 1 * RT + tid] = pa.y;
            s[OF_A0 + 2 * RT + tid] = pb.x;
            s[OF_A0 + 3 * RT + tid] = pb.y;
            s[OF_A0 + 4 * RT + tid] = pc.x;
            s[OF_A0 + 5 * RT + tid] = pc.y;
            srid[tid] = prid;
            int j = tb + K_CHUNKS * RT + tid;   // next tile for this CTA
            pa = make_float2(0.f, 0.f); pb = pa; pc = pa;
            if (j < count) {
                prid = g_rowids[off + j];
                const float2* ip = (const float2*)(inputs + 6 * prid);
                pa = ip[0]; pb = ip[1]; pc = ip[2];
            }
        }
        __syncthreads();

        gemm_tile<6>(s + OF_W0, s + OF_A0, s + OF_A1, s + OF_B, tx, wid);
        __syncthreads();
        gemm_tile<64>(s + OF_W1, s + OF_A1, s + OF_A0, s + OF_B + 64, tx, wid);
        __syncthreads();
        gemm_tile<64>(s + OF_W2, s + OF_A0, s + OF_A1, s + OF_B + 128, tx, wid);
        __syncthreads();
        gemm_tile<64>(s + OF_W3, s + OF_A1, s + OF_A0, s + OF_B + 192, tx, wid);
        __syncthreads();

        // final layer 64 -> 3 from A0: 2 threads per row (k split 32/32),
        // shfl-combine, even lane stores.
        if (tid < 2 * RT) {
            int row = tid >> 1, half = tid & 1;
            float acc0, acc1, acc2;
            if (half) { acc0 = 0.f; acc1 = 0.f; acc2 = 0.f; }
            else { acc0 = s[OF_B + 256]; acc1 = s[OF_B + 257]; acc2 = s[OF_B + 258]; }
            const float* a = s + OF_A0 + row;
            const float* wv = s + OF_W4;
            int kb = half * 32;
#pragma unroll 8
            for (int i = 0; i < 32; i++) {
                int k = kb + i;
                float av = a[k * RT];
                acc0 = fmaf(wv[k], av, acc0);
                acc1 = fmaf(wv[WP + k], av, acc1);
                acc2 = fmaf(wv[2 * WP + k], av, acc2);
            }
            acc0 += __shfl_down_sync(0xffffffffu, acc0, 1);
            acc1 += __shfl_down_sync(0xffffffffu, acc1, 1);
            acc2 += __shfl_down_sync(0xffffffffu, acc2, 1);
            if (!half && row < nrows) {
                int rid = srid[row];
                out_model[3 * rid + 0] = acc0;
                out_model[3 * rid + 1] = acc1;
                out_model[3 * rid + 2] = acc2;
                out_top[3 * rid + 0] = acc0;
                out_top[3 * rid + 1] = acc1;
                out_top[3 * rid + 2] = acc2;
            }
        }
    }
}

// ---------------------------------------------------------------------
extern "C" void kernel_launch(void* const* d_in, const int* in_sizes, int n_in,
                              void* d_out, int out_size) {
    const float* inputs = (const float*)d_in[0];
    const float* w0 = (const float*)d_in[1];
    const float* b0 = (const float*)d_in[2];
    const float* w1 = (const float*)d_in[3];
    const float* b1 = (const float*)d_in[4];
    const float* w2 = (const float*)d_in[5];
    const float* b2 = (const float*)d_in[6];
    const float* w3 = (const float*)d_in[7];
    const float* b3 = (const float*)d_in[8];
    const float* w4 = (const float*)d_in[9];
    const float* b4 = (const float*)d_in[10];

    int B = in_sizes[0] / IN_F;
    if (B > B_MAX) B = B_MAX;
    float* out = (float*)d_out;

    // output layout: model(3B) | top(3B) | idx(B) | logits(64B) | probs(64B)
    size_t Bs = (size_t)B;
    float* out_model = out;
    float* out_top = out + 3 * Bs;
    float* out_idx = out + 6 * Bs;
    float* out_logits = out + 7 * Bs;
    float* out_probs = out + 71 * Bs;

    cudaFuncSetAttribute(k_mlp, cudaFuncAttributeMaxDynamicSharedMemorySize,
                         SMEM_BYTES);

    k_fill<<<1024, 256>>>(out_logits, out_probs, B * 16);
    k_index<<<256, 256>>>(inputs, out_idx, B);
    k_scatter<<<256, 256>>>(B);
    k_mlp<<<NUM_MODELS * K_CHUNKS, TPB_MLP, SMEM_BYTES>>>(
        inputs, w0, b0, w1, b1, w2, b2, w3, b3, w4, b4, out_model, out_top);
}